// round 14
// baseline (speedup 1.0000x reference)
#include <cuda_runtime.h>

// Bilinear resample: B=16, S=128, C=128, fp32.
// R14: R13 body (one-wave grid-stride band schedule + pipelined offsets +
// evict-first stores, 32 regs) with incremental corner addressing:
// since x1-x0, y1-y0 ∈ {0,1}, compute p00 once and derive the other three
// corner addresses by adds/selects instead of four full address polynomials.
// Cuts ~15 issue slots per iteration off the serial address-compute head.

#define S 128
#define C 128
#define C4 (C / 4)                 // float4s per pixel
#define NPIX (16 * S * S)          // 262144
#define NPAIR (NPIX / 2)           // 131072
#define WARPS_PER_CTA 8            // 256 threads
#define NBLOCKS 1184               // one full wave at 8 CTAs/SM
#define NWARPS (NBLOCKS * WARPS_PER_CTA)   // 9472

#define ROWSTEP (S * C4)           // 4096 float4s between input rows
#define COLSTEP C4                 // 32 float4s between input cols

__device__ __forceinline__ float4 lerp4(float4 v00, float4 v01, float4 v10,
                                        float4 v11, float fx, float fy)
{
    float4 t, bo, o;
    t.x  = v00.x + (v01.x - v00.x) * fx;
    t.y  = v00.y + (v01.y - v00.y) * fx;
    t.z  = v00.z + (v01.z - v00.z) * fx;
    t.w  = v00.w + (v01.w - v00.w) * fx;
    bo.x = v10.x + (v11.x - v10.x) * fx;
    bo.y = v10.y + (v11.y - v10.y) * fx;
    bo.z = v10.z + (v11.z - v10.z) * fx;
    bo.w = v10.w + (v11.w - v10.w) * fx;
    o.x  = t.x + (bo.x - t.x) * fy;
    o.y  = t.y + (bo.y - t.y) * fy;
    o.z  = t.z + (bo.z - t.z) * fy;
    o.w  = t.w + (bo.w - t.w) * fy;
    return o;
}

// Corner base addresses for one pixel: p00 plus dx/dy increments.
__device__ __forceinline__ void corners(
    float offy, float offx, float fi, int j,
    int& p00, int& dxs, int& dys, float& fy, float& fx)
{
    const float y = fminf(fmaxf(offy + fi,       0.0f), (float)(S - 1));
    const float x = fminf(fmaxf(offx + (float)j, 0.0f), (float)(S - 1));
    const float y0f = floorf(y);
    const float x0f = floorf(x);
    const int y0 = (int)y0f;
    const int x0 = (int)x0f;
    const int y1 = (int)ceilf(y);   // y0 or y0+1 (reference semantics)
    const int x1 = (int)ceilf(x);
    fy = y - y0f;                   // row fraction
    fx = x - x0f;                   // col fraction
    p00 = y0 * ROWSTEP + x0 * COLSTEP;
    dxs = (x1 - x0) * COLSTEP;      // 0 or 32
    dys = (y1 - y0) * ROWSTEP;      // 0 or 4096
}

__global__ __launch_bounds__(256, 8) void resample_kernel(
    const float* __restrict__ offsets,
    const float* __restrict__ inputs,
    float* __restrict__ out)
{
    const int lane = threadIdx.x & 31;
    const int gw = blockIdx.x * WARPS_PER_CTA + (threadIdx.x >> 5);

    const float4* off4 = reinterpret_cast<const float4*>(offsets);
    const float4* in4  = reinterpret_cast<const float4*>(inputs);
    float4*       out4 = reinterpret_cast<float4*>(out);

    // Prologue: load first iteration's offsets.
    float4 off_next = (gw < NPAIR) ? __ldg(off4 + gw)
                                   : make_float4(0.f, 0.f, 0.f, 0.f);

#pragma unroll 1
    for (int p = gw; p < NPAIR; p += NWARPS) {
        const float4 off2 = off_next;
        const int pn = p + NWARPS;
        if (pn < NPAIR) off_next = __ldg(off4 + pn);   // overlaps gathers

        const int pix0 = p * 2;
        const int jA = pix0 & (S - 1);
        const int i  = (pix0 >> 7) & (S - 1);
        const int b  = pix0 >> 14;
        const float4* base = in4 + (size_t)b * (S * S * C4) + lane;
        const float fi = (float)i;

        int aP, aDX, aDY, bP, bDX, bDY;
        float afy, afx, bfy, bfx;
        corners(off2.x, off2.y, fi, jA,     aP, aDX, aDY, afy, afx);
        corners(off2.z, off2.w, fi, jA + 1, bP, bDX, bDY, bfy, bfx);

        // 8 independent coalesced 512B gathers (incremental addresses).
        const float4 a00 = __ldg(base + aP);
        const float4 a01 = __ldg(base + aP + aDX);
        const float4 a10 = __ldg(base + aP + aDY);
        const float4 a11 = __ldg(base + aP + aDY + aDX);
        const float4 b00 = __ldg(base + bP);
        const float4 b01 = __ldg(base + bP + bDX);
        const float4 b10 = __ldg(base + bP + bDY);
        const float4 b11 = __ldg(base + bP + bDY + bDX);

        float4* outp = out4 + (size_t)pix0 * C4 + lane;
        __stcs(outp,      lerp4(a00, a01, a10, a11, afx, afy));
        __stcs(outp + C4, lerp4(b00, b01, b10, b11, bfx, bfy));
    }
}

extern "C" void kernel_launch(void* const* d_in, const int* in_sizes, int n_in,
                              void* d_out, int out_size)
{
    const float* offsets = (const float*)d_in[0];
    const float* inputs  = (const float*)d_in[1];
    float* out = (float*)d_out;

    resample_kernel<<<NBLOCKS, WARPS_PER_CTA * 32>>>(offsets, inputs, out);
}

// round 15
// speedup vs baseline: 1.0894x; 1.0894x over previous
#include <cuda_runtime.h>

// Bilinear resample: B=16, S=128, C=128, fp32. FINAL (== R11, best measured).
//
// Structure and why each piece is there (all alternatives bench-falsified):
//  - warp = pixel pair, 8 INDEPENDENT coalesced 512B gathers per iteration
//    computed with independent address polynomials (incremental addressing
//    chained the loads and regressed: R14).
//  - one-full-wave launch (1184 CTAs) + warp-granularity grid-stride: the
//    machine's concurrent front is a contiguous ~9.3MB band of input rows,
//    so L2 absorbs the 4x corner overlap and DRAM traffic stays at the
//    compulsory ~230MB (chunked schedules hit 394MB: R8).
//  - software-pipelined offsets load: kills the second serial memory epoch
//    per iteration (~5us win: R10).
//  - evict-first output stores (__stcs): never-re-read write stream stays
//    out of L2's way (neutral-to-positive: R11).
//  - 32 registers, occ ~93%. Kernel runs at ~5.5TB/s on ~220MB moved --
//    ~95% of the best bandwidth observed on this part under any pattern.

#define S 128
#define C 128
#define C4 (C / 4)                 // float4s per pixel
#define NPIX (16 * S * S)          // 262144
#define NPAIR (NPIX / 2)           // 131072
#define WARPS_PER_CTA 8            // 256 threads
#define NBLOCKS 1184               // one full wave at 8 CTAs/SM
#define NWARPS (NBLOCKS * WARPS_PER_CTA)   // 9472

__device__ __forceinline__ float4 lerp4(float4 v00, float4 v01, float4 v10,
                                        float4 v11, float fx, float fy)
{
    float4 t, bo, o;
    t.x  = v00.x + (v01.x - v00.x) * fx;
    t.y  = v00.y + (v01.y - v00.y) * fx;
    t.z  = v00.z + (v01.z - v00.z) * fx;
    t.w  = v00.w + (v01.w - v00.w) * fx;
    bo.x = v10.x + (v11.x - v10.x) * fx;
    bo.y = v10.y + (v11.y - v10.y) * fx;
    bo.z = v10.z + (v11.z - v10.z) * fx;
    bo.w = v10.w + (v11.w - v10.w) * fx;
    o.x  = t.x + (bo.x - t.x) * fy;
    o.y  = t.y + (bo.y - t.y) * fy;
    o.z  = t.z + (bo.z - t.z) * fy;
    o.w  = t.w + (bo.w - t.w) * fy;
    return o;
}

__global__ __launch_bounds__(256, 7) void resample_kernel(
    const float* __restrict__ offsets,
    const float* __restrict__ inputs,
    float* __restrict__ out)
{
    const int lane = threadIdx.x & 31;
    const int gw = blockIdx.x * WARPS_PER_CTA + (threadIdx.x >> 5);

    const float4* off4 = reinterpret_cast<const float4*>(offsets);
    const float4* in4  = reinterpret_cast<const float4*>(inputs);
    float4*       out4 = reinterpret_cast<float4*>(out);

    // Prologue: load first iteration's offsets.
    float4 off_next = (gw < NPAIR) ? __ldg(off4 + gw)
                                   : make_float4(0.f, 0.f, 0.f, 0.f);

#pragma unroll 1
    for (int p = gw; p < NPAIR; p += NWARPS) {
        const float4 off2 = off_next;
        // Issue next iteration's offsets load NOW; it completes while this
        // iteration's gathers are in flight.
        const int pn = p + NWARPS;
        if (pn < NPAIR) off_next = __ldg(off4 + pn);

        const int pix0 = p * 2;
        const int jA = pix0 & (S - 1);
        const int i  = (pix0 >> 7) & (S - 1);
        const int b  = pix0 >> 14;
        const float4* base = in4 + (size_t)b * (S * S * C4);
        const float fi = (float)i;

        // Reference semantics: clip [0, S-1], rb = ceil.
        const float yA = fminf(fmaxf(off2.x + fi,              0.0f), (float)(S - 1));
        const float xA = fminf(fmaxf(off2.y + (float)jA,       0.0f), (float)(S - 1));
        const float yB = fminf(fmaxf(off2.z + fi,              0.0f), (float)(S - 1));
        const float xB = fminf(fmaxf(off2.w + (float)(jA + 1), 0.0f), (float)(S - 1));

        const float ay0f = floorf(yA), ax0f = floorf(xA);
        const float by0f = floorf(yB), bx0f = floorf(xB);
        const int aY0 = (int)ay0f,      aX0 = (int)ax0f;
        const int aY1 = (int)ceilf(yA), aX1 = (int)ceilf(xA);
        const int bY0 = (int)by0f,      bX0 = (int)bx0f;
        const int bY1 = (int)ceilf(yB), bX1 = (int)ceilf(xB);
        const float afy = yA - ay0f, afx = xA - ax0f;
        const float bfy = yB - by0f, bfx = xB - bx0f;

        // 8 independent coalesced 512B gathers.
        const float4 a00 = __ldg(base + (aY0 * S + aX0) * C4 + lane);
        const float4 a01 = __ldg(base + (aY0 * S + aX1) * C4 + lane);
        const float4 a10 = __ldg(base + (aY1 * S + aX0) * C4 + lane);
        const float4 a11 = __ldg(base + (aY1 * S + aX1) * C4 + lane);
        const float4 b00 = __ldg(base + (bY0 * S + bX0) * C4 + lane);
        const float4 b01 = __ldg(base + (bY0 * S + bX1) * C4 + lane);
        const float4 b10 = __ldg(base + (bY1 * S + bX0) * C4 + lane);
        const float4 b11 = __ldg(base + (bY1 * S + bX1) * C4 + lane);

        float4* outp = out4 + (size_t)pix0 * C4 + lane;
        __stcs(outp,      lerp4(a00, a01, a10, a11, afx, afy));
        __stcs(outp + C4, lerp4(b00, b01, b10, b11, bfx, bfy));
    }
}

extern "C" void kernel_launch(void* const* d_in, const int* in_sizes, int n_in,
                              void* d_out, int out_size)
{
    const float* offsets = (const float*)d_in[0];
    const float* inputs  = (const float*)d_in[1];
    float* out = (float*)d_out;

    resample_kernel<<<NBLOCKS, WARPS_PER_CTA * 32>>>(offsets, inputs, out);
}

// round 16
// speedup vs baseline: 1.0956x; 1.0056x over previous
#include <cuda_runtime.h>

// Bilinear resample: B=16, S=128, C=128, fp32.
// R16: R11's exact body and schedule (NWARPS identical -> same band-local
// grid-stride, same addresses), repartitioned into 128-thread CTAs:
// 16 CTAs/SM x 4 warps = 64 resident warps/SM (register file exactly full
// at 32 regs) vs 56 with 256-thr CTAs capped at 7 CTAs/SM. Pure
// latency-hiding increment; zero change to the byte stream.

#define S 128
#define C 128
#define C4 (C / 4)                 // float4s per pixel
#define NPIX (16 * S * S)          // 262144
#define NPAIR (NPIX / 2)           // 131072
#define WARPS_PER_CTA 4            // 128 threads
#define NBLOCKS 2368               // one full wave at 16 CTAs/SM
#define NWARPS (NBLOCKS * WARPS_PER_CTA)   // 9472 == R11 (schedule identical)

__device__ __forceinline__ float4 lerp4(float4 v00, float4 v01, float4 v10,
                                        float4 v11, float fx, float fy)
{
    float4 t, bo, o;
    t.x  = v00.x + (v01.x - v00.x) * fx;
    t.y  = v00.y + (v01.y - v00.y) * fx;
    t.z  = v00.z + (v01.z - v00.z) * fx;
    t.w  = v00.w + (v01.w - v00.w) * fx;
    bo.x = v10.x + (v11.x - v10.x) * fx;
    bo.y = v10.y + (v11.y - v10.y) * fx;
    bo.z = v10.z + (v11.z - v10.z) * fx;
    bo.w = v10.w + (v11.w - v10.w) * fx;
    o.x  = t.x + (bo.x - t.x) * fy;
    o.y  = t.y + (bo.y - t.y) * fy;
    o.z  = t.z + (bo.z - t.z) * fy;
    o.w  = t.w + (bo.w - t.w) * fy;
    return o;
}

__global__ __launch_bounds__(128, 16) void resample_kernel(
    const float* __restrict__ offsets,
    const float* __restrict__ inputs,
    float* __restrict__ out)
{
    const int lane = threadIdx.x & 31;
    const int gw = blockIdx.x * WARPS_PER_CTA + (threadIdx.x >> 5);

    const float4* off4 = reinterpret_cast<const float4*>(offsets);
    const float4* in4  = reinterpret_cast<const float4*>(inputs);
    float4*       out4 = reinterpret_cast<float4*>(out);

    // Prologue: load first iteration's offsets.
    float4 off_next = (gw < NPAIR) ? __ldg(off4 + gw)
                                   : make_float4(0.f, 0.f, 0.f, 0.f);

#pragma unroll 1
    for (int p = gw; p < NPAIR; p += NWARPS) {
        const float4 off2 = off_next;
        // Issue next iteration's offsets load NOW; it completes while this
        // iteration's gathers are in flight.
        const int pn = p + NWARPS;
        if (pn < NPAIR) off_next = __ldg(off4 + pn);

        const int pix0 = p * 2;
        const int jA = pix0 & (S - 1);
        const int i  = (pix0 >> 7) & (S - 1);
        const int b  = pix0 >> 14;
        const float4* base = in4 + (size_t)b * (S * S * C4);
        const float fi = (float)i;

        // Reference semantics: clip [0, S-1], rb = ceil.
        const float yA = fminf(fmaxf(off2.x + fi,              0.0f), (float)(S - 1));
        const float xA = fminf(fmaxf(off2.y + (float)jA,       0.0f), (float)(S - 1));
        const float yB = fminf(fmaxf(off2.z + fi,              0.0f), (float)(S - 1));
        const float xB = fminf(fmaxf(off2.w + (float)(jA + 1), 0.0f), (float)(S - 1));

        const float ay0f = floorf(yA), ax0f = floorf(xA);
        const float by0f = floorf(yB), bx0f = floorf(xB);
        const int aY0 = (int)ay0f,      aX0 = (int)ax0f;
        const int aY1 = (int)ceilf(yA), aX1 = (int)ceilf(xA);
        const int bY0 = (int)by0f,      bX0 = (int)bx0f;
        const int bY1 = (int)ceilf(yB), bX1 = (int)ceilf(xB);
        const float afy = yA - ay0f, afx = xA - ax0f;
        const float bfy = yB - by0f, bfx = xB - bx0f;

        // 8 independent coalesced 512B gathers.
        const float4 a00 = __ldg(base + (aY0 * S + aX0) * C4 + lane);
        const float4 a01 = __ldg(base + (aY0 * S + aX1) * C4 + lane);
        const float4 a10 = __ldg(base + (aY1 * S + aX0) * C4 + lane);
        const float4 a11 = __ldg(base + (aY1 * S + aX1) * C4 + lane);
        const float4 b00 = __ldg(base + (bY0 * S + bX0) * C4 + lane);
        const float4 b01 = __ldg(base + (bY0 * S + bX1) * C4 + lane);
        const float4 b10 = __ldg(base + (bY1 * S + bX0) * C4 + lane);
        const float4 b11 = __ldg(base + (bY1 * S + bX1) * C4 + lane);

        float4* outp = out4 + (size_t)pix0 * C4 + lane;
        __stcs(outp,      lerp4(a00, a01, a10, a11, afx, afy));
        __stcs(outp + C4, lerp4(b00, b01, b10, b11, bfx, bfy));
    }
}

extern "C" void kernel_launch(void* const* d_in, const int* in_sizes, int n_in,
                              void* d_out, int out_size)
{
    const float* offsets = (const float*)d_in[0];
    const float* inputs  = (const float*)d_in[1];
    float* out = (float*)d_out;

    resample_kernel<<<NBLOCKS, WARPS_PER_CTA * 32>>>(offsets, inputs, out);
}